// round 7
// baseline (speedup 1.0000x reference)
#include <cuda_runtime.h>
#include <cuda_bf16.h>

// F0 via raw autocorrelation argmax (per-frame normalization is a positive
// scalar -> argmax invariant -> skipped).
// R2: frame-pairs packed in f32x2, all inner math fma.rn.f32x2.
// R4: SHARED pair buffer. Since the pair interleave offset equals HOP, one
// buffer P[j] = (xpad[fb*HOP+j], xpad[fb*HOP+j+HOP]) serves all 8 pairs of the
// block at offsets p*512. Smem 47KB -> 32.8KB per block => occupancy 45%->~85%.
// Triangle masking (reads past frame index 511 must be zero) is done by
// clamping the feed address to a shared zero slot (1 SEL per step).

#define SR_I        16000
#define HOP         256
#define FRAME_LEN   512
#define MIN_PERIOD  32
#define LAGS_PER_LANE 7
#define PAIRS_PER_BLOCK 8      // 8 warps, each warp = 2 frames
#define T_LEN       163840
#define N_FRAMES    641
#define NBUF        4096       // 8 pairs * 512 stride; max read idx 7*512+511
#define ZSLOT       NBUF       // shared zero float2 slot

#define FMA_F32X2(d, a, b, c) \
    asm("fma.rn.f32x2 %0, %1, %2, %3;" : "=l"(d) : "l"(a), "l"(b), "l"(c))

__device__ __forceinline__ unsigned long long pack2(float2 v) {
    unsigned long long r;
    asm("mov.b64 %0, {%1, %2};" : "=l"(r) : "f"(v.x), "f"(v.y));
    return r;
}
__device__ __forceinline__ float2 unpack2(unsigned long long v) {
    float2 r;
    asm("mov.b64 {%0, %1}, %2;" : "=f"(r.x), "=f"(r.y) : "l"(v));
    return r;
}

__global__ __launch_bounds__(256) void f0_autocorr_sh_kernel(
    const float* __restrict__ x,   // (64, 1, 163840)
    float* __restrict__ out)       // (64, 641)
{
    __shared__ float2 P[NBUF + 1];

    const int b      = blockIdx.y;
    const int f_base = blockIdx.x * (2 * PAIRS_PER_BLOCK);   // first frame
    const float* __restrict__ xb = x + (size_t)b * T_LEN;
    const int tid = threadIdx.x;

    // Fill shared pair buffer: P[j] = (xpad[fb*HOP+j], xpad[fb*HOP+j+HOP]).
    // xpad[i] = x[reflect(i-256)] (numpy 'reflect', pad = 256). Raw indices are
    // reflected independently; raw1 = raw0 + HOP >= 0 always.
    for (int i = tid; i < NBUF + 1; i += 256) {
        float2 v = make_float2(0.0f, 0.0f);
        if (i < NBUF) {
            int g0 = f_base * HOP + i - (FRAME_LEN / 2);
            int g1 = g0 + HOP;
            if (g0 < 0) g0 = -g0;
            if (g0 >= T_LEN) g0 = 2 * (T_LEN - 1) - g0;
            if (g1 >= T_LEN) g1 = 2 * (T_LEN - 1) - g1;
            v.x = xb[g0];
            v.y = xb[g1];
        }
        P[i] = v;   // i == NBUF writes the zero slot
    }
    __syncthreads();

    const int w    = tid >> 5;              // warp = pair index
    const int lane = tid & 31;
    const int woff = w * (2 * HOP);         // pair offset into P
    const float2* __restrict__ Pw = P + woff;

    const int base = MIN_PERIOD + LAGS_PER_LANE * lane;   // 32..249

    unsigned long long acc[LAGS_PER_LANE];
    unsigned long long win[LAGS_PER_LANE];
#pragma unroll
    for (int k = 0; k < LAGS_PER_LANE; ++k) {
        acc[k] = 0ull;
        win[k] = pack2(Pw[base + k]);       // base+k <= 255 < 512: in-frame
    }

    // t = 0..479. Feed reads s[t+base+7]; once that index crosses the frame
    // boundary (512) it must be zero -> clamp address to the zero slot.
#pragma unroll 8
    for (int t = 0; t < FRAME_LEN - MIN_PERIOD; ++t) {
        const unsigned long long sb = pack2(Pw[t]);       // broadcast LDS.64
#pragma unroll
        for (int k = 0; k < LAGS_PER_LANE; ++k)
            FMA_F32X2(acc[k], sb, win[k], acc[k]);
#pragma unroll
        for (int k = 0; k < LAGS_PER_LANE - 1; ++k)
            win[k] = win[k + 1];
        const int jf  = t + base + LAGS_PER_LANE;         // next window sample
        const int idx = (jf < FRAME_LEN) ? (woff + jf) : ZSLOT;
        win[LAGS_PER_LANE - 1] = pack2(P[idx]);           // stride-7 conflict-free
    }

    // Per-lane argmax per packed frame (lowest lag wins ties).
    float bvx, bvy; int bpx, bpy;
    {
        float2 a0 = unpack2(acc[0]);
        bvx = a0.x; bvy = a0.y; bpx = base; bpy = base;
#pragma unroll
        for (int k = 1; k < LAGS_PER_LANE; ++k) {
            float2 a = unpack2(acc[k]);
            if (a.x > bvx) { bvx = a.x; bpx = base + k; }
            if (a.y > bvy) { bvy = a.y; bpy = base + k; }
        }
    }

    // Warp argmax, lowest-lag tie break.
#pragma unroll
    for (int off = 16; off > 0; off >>= 1) {
        const float ovx = __shfl_xor_sync(0xffffffffu, bvx, off);
        const int   opx = __shfl_xor_sync(0xffffffffu, bpx, off);
        const float ovy = __shfl_xor_sync(0xffffffffu, bvy, off);
        const int   opy = __shfl_xor_sync(0xffffffffu, bpy, off);
        if (ovx > bvx || (ovx == bvx && opx < bpx)) { bvx = ovx; bpx = opx; }
        if (ovy > bvy || (ovy == bvy && opy < bpy)) { bvy = ovy; bpy = opy; }
    }

    if (lane == 0) {
        const int f0 = f_base + 2 * w;
        if (f0 < N_FRAMES) {
            float r = (float)SR_I / ((float)bpx + 1e-8f);
            out[(size_t)b * N_FRAMES + f0] = fminf(fmaxf(r, 50.0f), 500.0f);
        }
        if (f0 + 1 < N_FRAMES) {
            float r = (float)SR_I / ((float)bpy + 1e-8f);
            out[(size_t)b * N_FRAMES + f0 + 1] = fminf(fmaxf(r, 50.0f), 500.0f);
        }
    }
}

extern "C" void kernel_launch(void* const* d_in, const int* in_sizes, int n_in,
                              void* d_out, int out_size)
{
    const float* x = (const float*)d_in[0];
    float* out = (float*)d_out;
    const int pairs = (N_FRAMES + 1) / 2;                       // 321
    dim3 grid((pairs + PAIRS_PER_BLOCK - 1) / PAIRS_PER_BLOCK,  // 41
              64);
    f0_autocorr_sh_kernel<<<grid, 256>>>(x, out);
}

// round 8
// speedup vs baseline: 1.4202x; 1.4202x over previous
#include <cuda_runtime.h>
#include <cuda_bf16.h>

// F0 via raw autocorrelation argmax (per-frame normalization is a positive
// scalar -> argmax invariant -> skipped).
// R2: frame-pairs packed in f32x2; all inner math fma.rn.f32x2 (private
//     zero-padded pair buffers -> triangle masking is free, no clamp ALU).
// R7: ping-pong window banks A/B with chunk prefetch. 16-step fully unrolled
//     body; each 8-step half-chunk consumes one bank while the other bank's
//     8 LDS.64 are in flight (load-to-use ~66 instr >> 29cyc LDS latency).
//     Kills the rolling-window serial chain that capped fma pipe at 64%.

#define SR_I        16000
#define HOP         256
#define FRAME_LEN   512
#define MIN_PERIOD  32
#define LAGS_PER_LANE 7
#define PAIRS_PER_BLOCK 8      // 8 warps, each warp = 2 frames
#define T_LEN       163840
#define N_FRAMES    641
#define BUF         740        // float2 slots; max read idx 736, zeros past 511

#define FMA_F32X2(d, a, b, c) \
    asm("fma.rn.f32x2 %0, %1, %2, %3;" : "=l"(d) : "l"(a), "l"(b), "l"(c))

__device__ __forceinline__ unsigned long long pack2(float2 v) {
    unsigned long long r;
    asm("mov.b64 %0, {%1, %2};" : "=l"(r) : "f"(v.x), "f"(v.y));
    return r;
}
__device__ __forceinline__ float2 unpack2(unsigned long long v) {
    float2 r;
    asm("mov.b64 {%0, %1}, %2;" : "=f"(r.x), "=f"(r.y) : "l"(v));
    return r;
}

__global__ __launch_bounds__(256) void f0_autocorr_pp_kernel(
    const float* __restrict__ x,   // (64, 1, 163840)
    float* __restrict__ out)       // (64, 641)
{
    __shared__ float2 sbuf[PAIRS_PER_BLOCK][BUF];

    const int b      = blockIdx.y;
    const int f_base = blockIdx.x * (2 * PAIRS_PER_BLOCK);
    const float* __restrict__ xb = x + (size_t)b * T_LEN;
    const int tid = threadIdx.x;

    // Fill: pair p holds frames (f_base+2p, f_base+2p+1) interleaved, then
    // zeros. xpad[j] = x[reflect(j-256)] (numpy 'reflect', pad = 256).
    for (int i = tid; i < PAIRS_PER_BLOCK * BUF; i += 256) {
        const int p = i / BUF;
        const int j = i - p * BUF;
        float2 v = make_float2(0.0f, 0.0f);
        if (j < FRAME_LEN) {
            const int fr = f_base + 2 * p;
            int g0 = fr * HOP + j - (FRAME_LEN / 2);
            int g1 = g0 + HOP;
            if (g0 < 0) g0 = -g0;
            if (g0 >= T_LEN) g0 = 2 * (T_LEN - 1) - g0;
            if (g1 >= T_LEN) g1 = 2 * (T_LEN - 1) - g1;
            v.x = xb[g0];
            v.y = xb[g1];
        }
        sbuf[p][j] = v;
    }
    __syncthreads();

    const int w    = tid >> 5;
    const int lane = tid & 31;
    const float2* __restrict__ s2 = sbuf[w];

    const int base = MIN_PERIOD + LAGS_PER_LANE * lane;   // 32..249

    unsigned long long acc[LAGS_PER_LANE];
#pragma unroll
    for (int k = 0; k < LAGS_PER_LANE; ++k) acc[k] = 0ull;

    // Bank A covers s[t+base .. t+base+7], bank B the next 8. Step j of a
    // half-chunk needs window s[t+j+base .. t+j+base+6] = values idx j..j+6
    // across (A,B). All selects are compile-time under full unroll.
    unsigned long long A[8], B[8];
#pragma unroll
    for (int k = 0; k < 8; ++k) A[k] = pack2(s2[base + k]);

    int t = 0;
#pragma unroll 1
    for (int c = 0; c < 30; ++c) {          // 30 * 16 = 480 steps
        // ---- half-chunk 1: window in A, prefetch B ----
#pragma unroll
        for (int k = 0; k < 8; ++k) B[k] = pack2(s2[t + base + 8 + k]);
#pragma unroll
        for (int j = 0; j < 8; ++j) {
            const unsigned long long sb = pack2(s2[t + j]);  // broadcast
#pragma unroll
            for (int k = 0; k < LAGS_PER_LANE; ++k) {
                const int idx = j + k;                       // 0..13
                FMA_F32X2(acc[k], sb, (idx < 8) ? A[idx] : B[idx - 8], acc[k]);
            }
        }
        t += 8;
        // ---- half-chunk 2: window in B, prefetch A ----
#pragma unroll
        for (int k = 0; k < 8; ++k) A[k] = pack2(s2[t + base + 8 + k]);
#pragma unroll
        for (int j = 0; j < 8; ++j) {
            const unsigned long long sb = pack2(s2[t + j]);
#pragma unroll
            for (int k = 0; k < LAGS_PER_LANE; ++k) {
                const int idx = j + k;
                FMA_F32X2(acc[k], sb, (idx < 8) ? B[idx] : A[idx - 8], acc[k]);
            }
        }
        t += 8;
    }

    // Per-lane argmax per packed frame (lowest lag wins ties).
    float bvx, bvy; int bpx, bpy;
    {
        float2 a0 = unpack2(acc[0]);
        bvx = a0.x; bvy = a0.y; bpx = base; bpy = base;
#pragma unroll
        for (int k = 1; k < LAGS_PER_LANE; ++k) {
            float2 a = unpack2(acc[k]);
            if (a.x > bvx) { bvx = a.x; bpx = base + k; }
            if (a.y > bvy) { bvy = a.y; bpy = base + k; }
        }
    }

    // Warp argmax, lowest-lag tie break.
#pragma unroll
    for (int off = 16; off > 0; off >>= 1) {
        const float ovx = __shfl_xor_sync(0xffffffffu, bvx, off);
        const int   opx = __shfl_xor_sync(0xffffffffu, bpx, off);
        const float ovy = __shfl_xor_sync(0xffffffffu, bvy, off);
        const int   opy = __shfl_xor_sync(0xffffffffu, bpy, off);
        if (ovx > bvx || (ovx == bvx && opx < bpx)) { bvx = ovx; bpx = opx; }
        if (ovy > bvy || (ovy == bvy && opy < bpy)) { bvy = ovy; bpy = opy; }
    }

    if (lane == 0) {
        const int fr = f_base + 2 * w;
        if (fr < N_FRAMES) {
            float r = (float)SR_I / ((float)bpx + 1e-8f);
            out[(size_t)b * N_FRAMES + fr] = fminf(fmaxf(r, 50.0f), 500.0f);
        }
        if (fr + 1 < N_FRAMES) {
            float r = (float)SR_I / ((float)bpy + 1e-8f);
            out[(size_t)b * N_FRAMES + fr + 1] = fminf(fmaxf(r, 50.0f), 500.0f);
        }
    }
}

extern "C" void kernel_launch(void* const* d_in, const int* in_sizes, int n_in,
                              void* d_out, int out_size)
{
    const float* x = (const float*)d_in[0];
    float* out = (float*)d_out;
    const int pairs = (N_FRAMES + 1) / 2;                       // 321
    dim3 grid((pairs + PAIRS_PER_BLOCK - 1) / PAIRS_PER_BLOCK,  // 41
              64);
    f0_autocorr_pp_kernel<<<grid, 256>>>(x, out);
}